// round 13
// baseline (speedup 1.0000x reference)
#include <cuda_runtime.h>
#include <cuda_fp16.h>
#include <cstdint>

#define PERIODS 12
#define ROWPAD 16          // xs/agg rows: 16 halves = 32B (1 sector)
#define HIDDEN 32
#define MAXN 100000
#define MAXE 1600000
#define TBINS 1024         // lookup bins over a in [-8, 8]

// Scratch (static __device__ — zero-initialized at module load; every launch
// restores the zero-invariant itself, so no init pass is needed).
__device__ float g_deg[MAXN];                             // invariant: 0 between launches
__device__ float g_dinv[MAXN];
__device__ __align__(32) __half g_aggh[MAXN * ROWPAD];    // invariant: 0 between launches
__device__ __align__(32) __half g_xsh[MAXN * ROWPAD];     // xs = dinv*x in fp16
__device__ __align__(16) float2 g_tbl[TBINS * HIDDEN];    // 256KB: (value, slope) per (bin, ch)

// Params as a flat float array for easy smem staging:
// [0:32) vz*0.5 | [32:64) cz*0.5 | [64:96) vh | [96:128) ch | [128:160) hw
// [160:172) probs | [172] head_b   => 173 floats
#define NPARAMS 173
__device__ float g_p[NPARAMS];

__device__ __forceinline__ float tanhx(float x) {
    float y;
    asm("tanh.approx.f32 %0, %1;" : "=f"(y) : "f"(x));
    return y;
}

// ---------------------------------------------------------------------------
// Fused: blocks [0, EB) accumulate deg[dst] += ew (from 0; self-loop folded
// into dinv later). Block EB folds the gate MLPs + softmax(attention).
// ---------------------------------------------------------------------------
__global__ void k_deg_params(int e, int eb,
                         const int* __restrict__ dst, const float* __restrict__ ew,
                         const float* __restrict__ att,
                         const float* __restrict__ czw, const float* __restrict__ czb,
                         const float* __restrict__ Lz,  const float* __restrict__ lzb,
                         const float* __restrict__ chw, const float* __restrict__ chb,
                         const float* __restrict__ Lh,  const float* __restrict__ lhb,
                         const float* __restrict__ head_w, const float* __restrict__ head_b) {
    if (blockIdx.x < (unsigned)eb) {
        int i = blockIdx.x * blockDim.x + threadIdx.x;
        if (i < e) atomicAdd(&g_deg[dst[i]], ew[i]);
        return;
    }
    // params block
    int c = threadIdx.x;
    if (c < HIDDEN) {
        float vz = 0.f, cz = 0.f, vh = 0.f, ch = 0.f;
        #pragma unroll
        for (int j = 0; j < HIDDEN; j++) {
            vz += czw[j] * Lz[j * HIDDEN + c];
            cz += czb[j] * Lz[j * HIDDEN + c];
            vh += chw[j] * Lh[j * HIDDEN + c];
            ch += chb[j] * Lh[j * HIDDEN + c];
        }
        g_p[c]       = vz * 0.5f;            // pre-halved for the sigmoid->tanh identity
        g_p[32 + c]  = (cz + lzb[c]) * 0.5f;
        g_p[64 + c]  = vh;
        g_p[96 + c]  = ch + lhb[c];
        g_p[128 + c] = head_w[c];
    }
    if (c == 0) {
        float m = att[0];
        for (int t = 1; t < PERIODS; t++) m = fmaxf(m, att[t]);
        float ex[PERIODS];
        float s = 0.f;
        for (int t = 0; t < PERIODS; t++) { ex[t] = __expf(att[t] - m); s += ex[t]; }
        float inv = 1.0f / s;
        for (int t = 0; t < PERIODS; t++) g_p[160 + t] = ex[t] * inv;
        g_p[172] = head_b[0];
    }
}

// Blocks [0, nb): dinv = (1 + deg)^{-1/2}; xs_h = fp16(dinv*x); reset deg.
// Blocks [nb, nb+TBINS/8): build the (value, slope) gate table from g_p.
__global__ void k_dinv_xs(const float4* __restrict__ x, int n, int nb) {
    if (blockIdx.x >= (unsigned)nb) {
        int idx = (blockIdx.x - nb) * blockDim.x + threadIdx.x;  // 0 .. TBINS*32-1
        int bin = idx >> 5, c = idx & 31;
        const float h = 16.0f / TBINS;
        float a0 = -8.0f + bin * h;
        float a1 = a0 + h;
        float vz = g_p[c], cz = g_p[32 + c];        // pre-halved
        float vh = g_p[64 + c], ch = g_p[96 + c];
        float g0 = (0.5f - 0.5f * tanhx(a0 * vz + cz)) * tanhx(a0 * vh + ch);
        float g1 = (0.5f - 0.5f * tanhx(a1 * vz + cz)) * tanhx(a1 * vh + ch);
        g_tbl[idx] = make_float2(g0, g1 - g0);
        return;
    }
    int i = blockIdx.x * blockDim.x + threadIdx.x;
    if (i < n) {
        float di = rsqrtf(1.0f + g_deg[i]);
        g_deg[i] = 0.0f;                          // restore zero-invariant
        g_dinv[i] = di;
        __half2* xshv = (__half2*)(g_xsh + i * ROWPAD);
        #pragma unroll
        for (int k = 0; k < 3; k++) {
            float4 v = x[i * 3 + k];              // x rows tight (12 floats)
            xshv[k * 2 + 0] = __floats2half2_rn(di * v.x, di * v.y);
            xshv[k * 2 + 1] = __floats2half2_rn(di * v.z, di * v.w);
        }
    }
}

// Per edge: agg[dst,:] += ew * xs_h[src,:]
// TWO edges per thread: vectorized int2/float2 stream loads, both gathers
// issued back-to-back (MLP=2), then v4.f16x2 + v2.f16x2 reds per edge.
__device__ __forceinline__ void edge_one(int s, int d, float c) {
    const uint4* xp = (const uint4*)(g_xsh + s * ROWPAD);
    uint4 q0 = xp[0];                       // halves 0..7
    uint2 q1 = ((const uint2*)xp)[2];       // halves 8..11
    __half* ap = g_aggh + d * ROWPAD;

    float2 f0 = __half22float2(*(__half2*)&q0.x);
    float2 f1 = __half22float2(*(__half2*)&q0.y);
    float2 f2 = __half22float2(*(__half2*)&q0.z);
    float2 f3 = __half22float2(*(__half2*)&q0.w);
    float2 f4 = __half22float2(*(__half2*)&q1.x);
    float2 f5 = __half22float2(*(__half2*)&q1.y);

    __half2 p0 = __floats2half2_rn(c * f0.x, c * f0.y);
    __half2 p1 = __floats2half2_rn(c * f1.x, c * f1.y);
    __half2 p2 = __floats2half2_rn(c * f2.x, c * f2.y);
    __half2 p3 = __floats2half2_rn(c * f3.x, c * f3.y);
    __half2 p4 = __floats2half2_rn(c * f4.x, c * f4.y);
    __half2 p5 = __floats2half2_rn(c * f5.x, c * f5.y);

    asm volatile("red.global.add.noftz.v4.f16x2 [%0], {%1,%2,%3,%4};"
                 :: "l"(ap),
                    "r"(*(unsigned*)&p0), "r"(*(unsigned*)&p1),
                    "r"(*(unsigned*)&p2), "r"(*(unsigned*)&p3) : "memory");
    asm volatile("red.global.add.noftz.v2.f16x2 [%0], {%1,%2};"
                 :: "l"(ap + 8),
                    "r"(*(unsigned*)&p4), "r"(*(unsigned*)&p5) : "memory");
}

__global__ void k_edge(const int* __restrict__ src,
                       const int* __restrict__ dst,
                       const float* __restrict__ ew,
                       int e) {
    int i = (blockIdx.x * blockDim.x + threadIdx.x) * 2;
    if (i + 1 < e) {
        int2   s2 = *(const int2*)(src + i);
        int2   d2 = *(const int2*)(dst + i);
        float2 w2 = *(const float2*)(ew + i);
        edge_one(s2.x, d2.x, w2.x);
        edge_one(s2.y, d2.y, w2.y);
    } else if (i < e) {
        edge_one(src[i], dst[i], ew[i]);
    }
}

// TWO nodes per warp. Staging computes per (node, t): table byte-offset + frac
// (ONCE per warp, not per lane), packed as float4 in smem. The inner loop is
// 1 broadcast LDS.128 + 2 lane-consecutive LDG.64 + 4 FMA — zero MUFU.
// a[n,t] = dinv*(agg_fp16[n,t] + dinv*x[n,t]); term = p * lerp(tbl[bin][c], fr).
// Resets agg rows to 0 for the next launch.
__global__ void k_node(const float* __restrict__ x, float* __restrict__ out, int n) {
    __shared__ float sp[NPARAMS];
    __shared__ float4 sa[8][PERIODS];               // 8 warps/block; 16B aligned
    if (threadIdx.x < NPARAMS) sp[threadIdx.x] = g_p[threadIdx.x];
    __syncthreads();

    int warp = (blockIdx.x * blockDim.x + threadIdx.x) >> 5;
    int wlocal = (threadIdx.x >> 5);
    int lane = threadIdx.x & 31;
    int nodeA = warp * 2;
    int nodeB = nodeA + 1;
    if (nodeA >= n) return;
    bool hasB = nodeB < n;

    float diA = g_dinv[nodeA];
    float diB = hasB ? g_dinv[nodeB] : 0.f;
    float aval = 0.f;
    if (lane < PERIODS) {
        float edge = __half2float(g_aggh[nodeA * ROWPAD + lane]);
        aval = diA * (edge + diA * x[nodeA * PERIODS + lane]);
    } else if (lane >= 16 && lane < 16 + PERIODS) {
        int l = lane - 16;
        float edge = hasB ? __half2float(g_aggh[nodeB * ROWPAD + l]) : 0.f;
        float xv   = hasB ? x[nodeB * PERIODS + l] : 0.f;
        aval = diB * (edge + diB * xv);
    }
    // per-lane bin/frac: u = (a + 8) * (TBINS/16), clamped
    float u = fminf(fmaxf(fmaf(aval, TBINS / 16.0f, TBINS / 2.0f), 0.0f),
                    (float)(TBINS - 1) - 0.001f);
    int   bin = (int)u;
    float fr  = u - (float)bin;
    int   off = bin << 8;                           // bin * 32 entries * 8B
    float offB = __shfl_down_sync(0xffffffffu, __int_as_float(off), 16);
    float frB  = __shfl_down_sync(0xffffffffu, fr, 16);
    if (lane < PERIODS) {
        float4 pk; pk.x = __int_as_float(off); pk.y = fr; pk.z = offB; pk.w = frB;
        sa[wlocal][lane] = pk;                      // st.shared.v4 (aligned)
    }
    __syncwarp();
    // restore zero-invariant: halves 0..11 of each row (padding never written)
    if (lane < 6)
        ((unsigned*)(g_aggh + nodeA * ROWPAD))[lane] = 0u;
    else if (lane >= 16 && lane < 22 && hasB)
        ((unsigned*)(g_aggh + nodeB * ROWPAD))[lane - 16] = 0u;

    const char* tb = (const char*)g_tbl + lane * 8; // per-lane channel column
    float hA = 0.f, hB = 0.f;
    #pragma unroll
    for (int t = 0; t < PERIODS; t++) {
        float p   = sp[160 + t];
        float4 q  = sa[wlocal][t];                  // broadcast LDS.128
        float2 vA = __ldg((const float2*)(tb + __float_as_int(q.x)));
        float2 vB = __ldg((const float2*)(tb + __float_as_int(q.z)));
        hA = fmaf(p, fmaf(q.y, vA.y, vA.x), hA);
        hB = fmaf(p, fmaf(q.w, vB.y, vB.x), hB);
    }
    float vA = fmaxf(hA, 0.f) * sp[128 + lane];
    float vB = fmaxf(hB, 0.f) * sp[128 + lane];
    #pragma unroll
    for (int off2 = 16; off2; off2 >>= 1) {
        vA += __shfl_xor_sync(0xffffffffu, vA, off2);
        vB += __shfl_xor_sync(0xffffffffu, vB, off2);
    }
    if (lane == 0) {
        float hb = sp[172];
        out[nodeA] = vA + hb;
        if (hasB) out[nodeB] = vB + hb;
    }
}

extern "C" void kernel_launch(void* const* d_in, const int* in_sizes, int n_in,
                              void* d_out, int out_size) {
    const float* x    = (const float*)d_in[0];
    const int*   eidx = (const int*)d_in[1];   // int32 (JAX x64 disabled)
    const float* ew   = (const float*)d_in[2];
    const float* att  = (const float*)d_in[3];
    const float* czw  = (const float*)d_in[4];
    const float* czb  = (const float*)d_in[5];
    const float* lzw  = (const float*)d_in[6];
    const float* lzb  = (const float*)d_in[7];
    // d_in[8..11]: r-gate params — provably unused (H = 0 => H*R = 0)
    const float* chw  = (const float*)d_in[12];
    const float* chb  = (const float*)d_in[13];
    const float* lhw  = (const float*)d_in[14];
    const float* lhb  = (const float*)d_in[15];
    const float* hw   = (const float*)d_in[16];
    const float* hb   = (const float*)d_in[17];
    float* out = (float*)d_out;

    int N = in_sizes[0] / PERIODS;
    int E = in_sizes[2];
    const int* src = eidx;
    const int* dst = eidx + E;

    int EB = (E + 255) / 256;
    k_deg_params<<<EB + 1, 256>>>(E, EB, dst, ew, att, czw, czb, lzw, lzb,
                                  chw, chb, lhw, lhb, hw, hb);

    int NB = (N + 255) / 256;
    k_dinv_xs<<<NB + (TBINS * HIDDEN) / 256, 256>>>((const float4*)x, N, NB);

    int ethreads = (E + 1) / 2;                    // 2 edges per thread
    k_edge<<<(ethreads + 255) / 256, 256>>>(src, dst, ew, E);

    int pairs = (N + 1) / 2;                       // one warp per 2 nodes
    k_node<<<(pairs * 32 + 255) / 256, 256>>>(x, out, N);
}

// round 14
// speedup vs baseline: 1.0369x; 1.0369x over previous
#include <cuda_runtime.h>
#include <cuda_fp16.h>
#include <cstdint>

#define PERIODS 12
#define ROWPAD 16          // xs/agg rows: 16 halves = 32B (1 sector)
#define HIDDEN 32
#define MAXN 100000
#define MAXE 1600000

// Scratch (static __device__ — zero-initialized at module load; every launch
// restores the zero-invariant itself, so no init pass is needed).
__device__ float g_deg[MAXN];                             // invariant: 0 between launches
__device__ float g_dinv[MAXN];
__device__ __align__(32) __half g_aggh[MAXN * ROWPAD];    // invariant: 0 between launches
__device__ __align__(32) __half g_xsh[MAXN * ROWPAD];     // xs = dinv*x in fp16

// Params as a flat float array for easy smem staging:
// [0:32) vz*0.5 | [32:64) cz*0.5 | [64:96) vh | [96:128) ch | [128:160) hw
// [160:172) probs | [172] head_b   => 173 floats
#define NPARAMS 173
__device__ float g_p[NPARAMS];

__device__ __forceinline__ float tanhx(float x) {
    float y;
    asm("tanh.approx.f32 %0, %1;" : "=f"(y) : "f"(x));
    return y;
}

// ---------------------------------------------------------------------------
// Fused: blocks [0, eb) accumulate deg[dst] += ew, TWO edges per thread
// (vectorized stream loads). Block eb folds the gate MLPs + softmax(att).
// ---------------------------------------------------------------------------
__global__ void k_deg_params(int e, int eb,
                         const int* __restrict__ dst, const float* __restrict__ ew,
                         const float* __restrict__ att,
                         const float* __restrict__ czw, const float* __restrict__ czb,
                         const float* __restrict__ Lz,  const float* __restrict__ lzb,
                         const float* __restrict__ chw, const float* __restrict__ chb,
                         const float* __restrict__ Lh,  const float* __restrict__ lhb,
                         const float* __restrict__ head_w, const float* __restrict__ head_b) {
    if (blockIdx.x < (unsigned)eb) {
        int i = (blockIdx.x * blockDim.x + threadIdx.x) * 2;
        if (i + 1 < e) {
            int2   d2 = *(const int2*)(dst + i);
            float2 w2 = *(const float2*)(ew + i);
            atomicAdd(&g_deg[d2.x], w2.x);
            atomicAdd(&g_deg[d2.y], w2.y);
        } else if (i < e) {
            atomicAdd(&g_deg[dst[i]], ew[i]);
        }
        return;
    }
    // params block
    int c = threadIdx.x;
    if (c < HIDDEN) {
        float vz = 0.f, cz = 0.f, vh = 0.f, ch = 0.f;
        #pragma unroll
        for (int j = 0; j < HIDDEN; j++) {
            vz += czw[j] * Lz[j * HIDDEN + c];
            cz += czb[j] * Lz[j * HIDDEN + c];
            vh += chw[j] * Lh[j * HIDDEN + c];
            ch += chb[j] * Lh[j * HIDDEN + c];
        }
        g_p[c]       = vz * 0.5f;            // pre-halved for the sigmoid->tanh identity
        g_p[32 + c]  = (cz + lzb[c]) * 0.5f;
        g_p[64 + c]  = vh;
        g_p[96 + c]  = ch + lhb[c];
        g_p[128 + c] = head_w[c];
    }
    if (c == 0) {
        float m = att[0];
        for (int t = 1; t < PERIODS; t++) m = fmaxf(m, att[t]);
        float ex[PERIODS];
        float s = 0.f;
        for (int t = 0; t < PERIODS; t++) { ex[t] = __expf(att[t] - m); s += ex[t]; }
        float inv = 1.0f / s;
        for (int t = 0; t < PERIODS; t++) g_p[160 + t] = ex[t] * inv;
        g_p[172] = head_b[0];
    }
}

// dinv = (1 + deg)^{-1/2} (self loop folded);  xs_h = fp16(dinv*x);
// resets g_deg to 0 for the next launch.
__global__ void k_dinv_xs(const float4* __restrict__ x, int n) {
    int i = blockIdx.x * blockDim.x + threadIdx.x;
    if (i < n) {
        float di = rsqrtf(1.0f + g_deg[i]);
        g_deg[i] = 0.0f;                          // restore zero-invariant
        g_dinv[i] = di;
        __half2* xshv = (__half2*)(g_xsh + i * ROWPAD);
        #pragma unroll
        for (int k = 0; k < 3; k++) {
            float4 v = x[i * 3 + k];              // x rows tight (12 floats)
            xshv[k * 2 + 0] = __floats2half2_rn(di * v.x, di * v.y);
            xshv[k * 2 + 1] = __floats2half2_rn(di * v.z, di * v.w);
        }
    }
}

// Per edge: agg[dst,:] += ew * xs_h[src,:]
// TWO edges per thread: vectorized int2/float2 stream loads, both gathers
// issued back-to-back (MLP=2), then v4.f16x2 + v2.f16x2 reds per edge.
__device__ __forceinline__ void edge_one(int s, int d, float c) {
    const uint4* xp = (const uint4*)(g_xsh + s * ROWPAD);
    uint4 q0 = xp[0];                       // halves 0..7
    uint2 q1 = ((const uint2*)xp)[2];       // halves 8..11
    __half* ap = g_aggh + d * ROWPAD;

    float2 f0 = __half22float2(*(__half2*)&q0.x);
    float2 f1 = __half22float2(*(__half2*)&q0.y);
    float2 f2 = __half22float2(*(__half2*)&q0.z);
    float2 f3 = __half22float2(*(__half2*)&q0.w);
    float2 f4 = __half22float2(*(__half2*)&q1.x);
    float2 f5 = __half22float2(*(__half2*)&q1.y);

    __half2 p0 = __floats2half2_rn(c * f0.x, c * f0.y);
    __half2 p1 = __floats2half2_rn(c * f1.x, c * f1.y);
    __half2 p2 = __floats2half2_rn(c * f2.x, c * f2.y);
    __half2 p3 = __floats2half2_rn(c * f3.x, c * f3.y);
    __half2 p4 = __floats2half2_rn(c * f4.x, c * f4.y);
    __half2 p5 = __floats2half2_rn(c * f5.x, c * f5.y);

    asm volatile("red.global.add.noftz.v4.f16x2 [%0], {%1,%2,%3,%4};"
                 :: "l"(ap),
                    "r"(*(unsigned*)&p0), "r"(*(unsigned*)&p1),
                    "r"(*(unsigned*)&p2), "r"(*(unsigned*)&p3) : "memory");
    asm volatile("red.global.add.noftz.v2.f16x2 [%0], {%1,%2};"
                 :: "l"(ap + 8),
                    "r"(*(unsigned*)&p4), "r"(*(unsigned*)&p5) : "memory");
}

__global__ void k_edge(const int* __restrict__ src,
                       const int* __restrict__ dst,
                       const float* __restrict__ ew,
                       int e) {
    int i = (blockIdx.x * blockDim.x + threadIdx.x) * 2;
    if (i + 1 < e) {
        int2   s2 = *(const int2*)(src + i);
        int2   d2 = *(const int2*)(dst + i);
        float2 w2 = *(const float2*)(ew + i);
        edge_one(s2.x, d2.x, w2.x);
        edge_one(s2.y, d2.y, w2.y);
    } else if (i < e) {
        edge_one(src[i], dst[i], ew[i]);
    }
}

// FOUR consecutive nodes per warp (tanh core — table reverted).
// Staging: lane = (r, j) with r = lane>>3 (node), j = lane&7 (period pair, j<6):
// one coalesced LDG.32 over the 4 contiguous agg rows + one LDG.64 from x,
// a-values written transposed into float4 sa[warp][t] (LDS.128 broadcast in loop).
// a[n,t] = dinv*(agg_fp16[n,t] + dinv*x[n,t]); term = p*(0.5-0.5*tanh(xz/2))*tanh(xh).
// Resets agg rows to 0 for the next launch.
__global__ void k_node(const float* __restrict__ x, float* __restrict__ out, int n) {
    __shared__ float sp[NPARAMS];
    __shared__ float4 sa[8][PERIODS];               // 8 warps/block; 16B aligned
    if (threadIdx.x < NPARAMS) sp[threadIdx.x] = g_p[threadIdx.x];
    __syncthreads();

    int warp = (blockIdx.x * blockDim.x + threadIdx.x) >> 5;
    int wl = threadIdx.x >> 5;
    int lane = threadIdx.x & 31;
    int base = warp * 4;
    if (base >= n) return;

    int r = lane >> 3, j = lane & 7;
    int node = base + r;
    if (j < 6 && node < n) {
        float di = g_dinv[node];
        unsigned pair = ((const unsigned*)(g_aggh + node * ROWPAD))[j];  // t=2j,2j+1
        float2 xv = *(const float2*)(x + node * PERIODS + 2 * j);
        float2 ef = __half22float2(*(__half2*)&pair);
        float a0 = di * (ef.x + di * xv.x);
        float a1 = di * (ef.y + di * xv.y);
        float* s0 = (float*)&sa[wl][2 * j];
        s0[r]     = a0;                              // sa[wl][2j].{r}
        s0[4 + r] = a1;                              // sa[wl][2j+1].{r}
    }
    // zero restore: halves 0..11 of the 4 rows (24 uints), padding never written
    if (lane < 24) {
        int node2 = base + lane / 6;
        if (node2 < n)
            ((unsigned*)(g_aggh + node2 * ROWPAD))[lane % 6] = 0u;
    }
    __syncwarp();

    float vz = sp[lane],      cz = sp[32 + lane];   // pre-halved
    float vh = sp[64 + lane], ch = sp[96 + lane];

    float h0 = 0.f, h1 = 0.f, h2 = 0.f, h3 = 0.f;
    #pragma unroll
    for (int t = 0; t < PERIODS; t++) {
        float p  = sp[160 + t];
        float4 q = sa[wl][t];                       // broadcast LDS.128
        float tz0 = tanhx(q.x * vz + cz), th0 = tanhx(q.x * vh + ch);
        float tz1 = tanhx(q.y * vz + cz), th1 = tanhx(q.y * vh + ch);
        float tz2 = tanhx(q.z * vz + cz), th2 = tanhx(q.z * vh + ch);
        float tz3 = tanhx(q.w * vz + cz), th3 = tanhx(q.w * vh + ch);
        h0 += p * ((0.5f - 0.5f * tz0) * th0);
        h1 += p * ((0.5f - 0.5f * tz1) * th1);
        h2 += p * ((0.5f - 0.5f * tz2) * th2);
        h3 += p * ((0.5f - 0.5f * tz3) * th3);
    }
    float hw = sp[128 + lane];
    float v0 = fmaxf(h0, 0.f) * hw;
    float v1 = fmaxf(h1, 0.f) * hw;
    float v2 = fmaxf(h2, 0.f) * hw;
    float v3 = fmaxf(h3, 0.f) * hw;
    #pragma unroll
    for (int off = 16; off; off >>= 1) {
        v0 += __shfl_xor_sync(0xffffffffu, v0, off);
        v1 += __shfl_xor_sync(0xffffffffu, v1, off);
        v2 += __shfl_xor_sync(0xffffffffu, v2, off);
        v3 += __shfl_xor_sync(0xffffffffu, v3, off);
    }
    if (lane == 0) {
        float hb = sp[172];
        if (base + 3 < n) {
            *(float4*)(out + base) = make_float4(v0 + hb, v1 + hb, v2 + hb, v3 + hb);
        } else {
            out[base] = v0 + hb;
            if (base + 1 < n) out[base + 1] = v1 + hb;
            if (base + 2 < n) out[base + 2] = v2 + hb;
        }
    }
}

extern "C" void kernel_launch(void* const* d_in, const int* in_sizes, int n_in,
                              void* d_out, int out_size) {
    const float* x    = (const float*)d_in[0];
    const int*   eidx = (const int*)d_in[1];   // int32 (JAX x64 disabled)
    const float* ew   = (const float*)d_in[2];
    const float* att  = (const float*)d_in[3];
    const float* czw  = (const float*)d_in[4];
    const float* czb  = (const float*)d_in[5];
    const float* lzw  = (const float*)d_in[6];
    const float* lzb  = (const float*)d_in[7];
    // d_in[8..11]: r-gate params — provably unused (H = 0 => H*R = 0)
    const float* chw  = (const float*)d_in[12];
    const float* chb  = (const float*)d_in[13];
    const float* lhw  = (const float*)d_in[14];
    const float* lhb  = (const float*)d_in[15];
    const float* hw   = (const float*)d_in[16];
    const float* hb   = (const float*)d_in[17];
    float* out = (float*)d_out;

    int N = in_sizes[0] / PERIODS;
    int E = in_sizes[2];
    const int* src = eidx;
    const int* dst = eidx + E;

    int EB = (E / 2 + 255) / 256;                  // 2 edges per thread
    k_deg_params<<<EB + 1, 256>>>(E, EB, dst, ew, att, czw, czb, lzw, lzb,
                                  chw, chb, lhw, lhb, hw, hb);

    k_dinv_xs<<<(N + 255) / 256, 256>>>((const float4*)x, N);

    int ethreads = (E + 1) / 2;                    // 2 edges per thread
    k_edge<<<(ethreads + 255) / 256, 256>>>(src, dst, ew, E);

    int quads = (N + 3) / 4;                       // one warp per 4 nodes
    k_node<<<(quads * 32 + 255) / 256, 256>>>(x, out, N);
}